// round 1
// baseline (speedup 1.0000x reference)
#include <cuda_runtime.h>
#include <cstdint>
#include <cstdio>

// ===================== problem constants =====================
#define BB 128
#define TT 2048

// ===================== static device scratch =====================
// Two ping-pong sequence buffers sized for the largest channel count (175).
__device__ float g_bufA[(size_t)BB * TT * 175];
__device__ float g_bufB[(size_t)BB * TT * 175];
__device__ float g_mask[(size_t)BB * TT];
__device__ float g_h34[BB * 60];
__device__ float g_z[BB * 30];
__device__ float g_Uc[60 * 180];
__device__ float g_Wc[150 * 180];
__device__ float g_bc[2 * 180];

// ===================== helpers =====================
__host__ __device__ constexpr int padDim(int v) {
    int h = (v + 3) / 4 * 4;
    if (((h / 4) & 1) == 0) h += 4;   // ensure (h/4) odd -> conflict-free 8-way strides
    return h;
}

__device__ __forceinline__ uint32_t smem_u32(const void* p) {
    uint32_t a;
    asm("{ .reg .u64 t; cvta.to.shared.u64 t, %1; cvt.u32.u64 %0, t; }" : "=r"(a) : "l"(p));
    return a;
}
__device__ __forceinline__ uint32_t mapa_shared(uint32_t local, uint32_t rank) {
    uint32_t r;
    asm("mapa.shared::cluster.u32 %0, %1, %2;" : "=r"(r) : "r"(local), "r"(rank));
    return r;
}
__device__ __forceinline__ void st_cluster_f32(uint32_t addr, float v) {
    asm volatile("st.shared::cluster.b32 [%0], %1;" :: "r"(addr), "r"(__float_as_uint(v)));
}
__device__ __forceinline__ void cluster_sync_() {
    asm volatile("barrier.cluster.arrive.aligned;" ::: "memory");
    asm volatile("barrier.cluster.wait.aligned;" ::: "memory");
}

__device__ __forceinline__ float hsig(float v) { return fminf(fmaxf(0.2f * v + 0.5f, 0.f), 1.f); }
__device__ __forceinline__ float sigm(float v) { return 1.f / (1.f + expf(-v)); }

// ===================== generic persistent GRU kernel =====================
// Cluster of 8 CTAs handles 8 batch rows; CTA r owns hidden-column tile r.
// Weights cached in smem (all 2048 steps); h double-buffered, replicated per CTA,
// exchanged via DSMEM stores + one cluster barrier per step.
template <int H, int I, bool HARDSIG, bool TANHACT, bool USEMASK, bool WRITESEQ>
__global__ void __cluster_dims__(8, 1, 1) __launch_bounds__(256, 1)
gru_kernel(const float* __restrict__ in_seq, const float* __restrict__ U,
           const float* __restrict__ W, const float* __restrict__ bias,
           const float* __restrict__ mask, float* __restrict__ out_seq)
{
    constexpr int GJ = 8, BT = 8;
    constexpr int JT = (H + GJ - 1) / GJ;
    constexpr int HP = padDim(H), IP = padDim(I);
    static_assert(BT * JT <= 256, "unit count exceeds CTA threads");

    extern __shared__ float smem[];
    float* sUz = smem;
    float* sUr = sUz + JT * HP;
    float* sUh = sUr + JT * HP;
    float* sWz = sUh + JT * HP;
    float* sWr = sWz + JT * IP;
    float* sWh = sWr + JT * IP;
    float* sh  = sWh + JT * IP;          // 2 * BT * HP (double buffer)
    float* sx  = sh  + 2 * BT * HP;      // BT * IP
    float* sbz = sx  + BT * IP;
    float* sbr = sbz + JT;
    float* sbxh = sbr + JT;
    float* sbrh = sbxh + JT;
    float* smk  = sbrh + JT;             // BT

    const int tid  = threadIdx.x;
    const int rank = blockIdx.x & 7;
    const int ci   = blockIdx.x >> 3;
    const int b0   = ci * BT;
    const int j0   = rank * JT;

    constexpr int SM_TOT = 3 * JT * HP + 3 * JT * IP + 2 * BT * HP + BT * IP + 4 * JT + BT;
    for (int e = tid; e < SM_TOT; e += 256) smem[e] = 0.f;
    __syncthreads();

    // fill weight tiles (column-major per hidden unit, zero-padded)
    for (int e = tid; e < JT * H; e += 256) {
        int jj = e / H, k = e % H;
        int j = j0 + jj;
        if (j < H) {
            sUz[jj * HP + k] = U[k * 3 * H + j];
            sUr[jj * HP + k] = U[k * 3 * H + H + j];
            sUh[jj * HP + k] = U[k * 3 * H + 2 * H + j];
        }
    }
    for (int e = tid; e < JT * I; e += 256) {
        int jj = e / I, i = e % I;
        int j = j0 + jj;
        if (j < H) {
            sWz[jj * IP + i] = W[i * 3 * H + j];
            sWr[jj * IP + i] = W[i * 3 * H + H + j];
            sWh[jj * IP + i] = W[i * 3 * H + 2 * H + j];
        }
    }
    if (tid < JT) {
        int j = j0 + tid;
        if (j < H) {
            sbz[tid]  = bias[j] + bias[3 * H + j];
            sbr[tid]  = bias[H + j] + bias[3 * H + H + j];
            sbxh[tid] = bias[2 * H + j];
            sbrh[tid] = bias[3 * H + 2 * H + j];
        }
    }
    __syncthreads();

    // remote h-buffer bases for DSMEM broadcast
    uint32_t sh_local = smem_u32(sh);
    uint32_t rbase[GJ];
#pragma unroll
    for (int r = 0; r < GJ; r++) rbase[r] = mapa_shared(sh_local, (uint32_t)r);

    cluster_sync_();   // everyone's smem initialized before any remote write

    const int b  = tid % BT;
    const int jj = tid / BT;
    const int j  = j0 + jj;
    const bool active = (jj < JT) && (j < H);

    int p = 0;
    for (int t = 0; t < TT; t++) {
        // stage x_t (and step mask) into smem
        for (int e = tid; e < BT * I; e += 256) {
            int bb = e / I, i = e % I;
            sx[bb * IP + i] = in_seq[((size_t)(b0 + bb) * TT + t) * I + i];
        }
        if (USEMASK && tid < BT) smk[tid] = mask[(size_t)(b0 + tid) * TT + t];
        __syncthreads();

        if (active) {
            float az = sbz[jj], ar = sbr[jj], arh = sbrh[jj], axh = sbxh[jj];
            const float4* hv = (const float4*)(sh + p * BT * HP + b * HP);
            const float4* uz = (const float4*)(sUz + jj * HP);
            const float4* ur = (const float4*)(sUr + jj * HP);
            const float4* uh = (const float4*)(sUh + jj * HP);
            for (int k4 = 0; k4 < HP / 4; ++k4) {
                float4 h4 = hv[k4];
                float4 z4 = uz[k4];
                float4 r4 = ur[k4];
                float4 g4 = uh[k4];
                az  = fmaf(h4.x, z4.x, az);  az  = fmaf(h4.y, z4.y, az);
                az  = fmaf(h4.z, z4.z, az);  az  = fmaf(h4.w, z4.w, az);
                ar  = fmaf(h4.x, r4.x, ar);  ar  = fmaf(h4.y, r4.y, ar);
                ar  = fmaf(h4.z, r4.z, ar);  ar  = fmaf(h4.w, r4.w, ar);
                arh = fmaf(h4.x, g4.x, arh); arh = fmaf(h4.y, g4.y, arh);
                arh = fmaf(h4.z, g4.z, arh); arh = fmaf(h4.w, g4.w, arh);
            }
            const float4* xv = (const float4*)(sx + b * IP);
            const float4* wz = (const float4*)(sWz + jj * IP);
            const float4* wr = (const float4*)(sWr + jj * IP);
            const float4* wh = (const float4*)(sWh + jj * IP);
            for (int i4 = 0; i4 < IP / 4; ++i4) {
                float4 x4 = xv[i4];
                float4 z4 = wz[i4];
                float4 r4 = wr[i4];
                float4 g4 = wh[i4];
                az  = fmaf(x4.x, z4.x, az);  az  = fmaf(x4.y, z4.y, az);
                az  = fmaf(x4.z, z4.z, az);  az  = fmaf(x4.w, z4.w, az);
                ar  = fmaf(x4.x, r4.x, ar);  ar  = fmaf(x4.y, r4.y, ar);
                ar  = fmaf(x4.z, r4.z, ar);  ar  = fmaf(x4.w, r4.w, ar);
                axh = fmaf(x4.x, g4.x, axh); axh = fmaf(x4.y, g4.y, axh);
                axh = fmaf(x4.z, g4.z, axh); axh = fmaf(x4.w, g4.w, axh);
            }
            float z = HARDSIG ? hsig(az) : sigm(az);
            float r = HARDSIG ? hsig(ar) : sigm(ar);
            float hh = axh + r * arh;
            if (TANHACT) hh = tanhf(hh);
            float hprev = sh[p * BT * HP + b * HP + j];
            float hn = z * hprev + (1.f - z) * hh;
            if (USEMASK) { if (smk[b] == 0.f) hn = hprev; }

            uint32_t off = (uint32_t)(((1 - p) * BT * HP + b * HP + j) * 4);
#pragma unroll
            for (int r2 = 0; r2 < GJ; r2++) st_cluster_f32(rbase[r2] + off, hn);

            if (WRITESEQ) out_seq[((size_t)(b0 + b) * TT + t) * H + j] = hn;
        }
        cluster_sync_();
        p ^= 1;
    }

    if (!WRITESEQ) {
        if (active) out_seq[(size_t)(b0 + b) * H + j] = sh[p * BT * HP + b * HP + j];
    }
}

// ===================== small kernels =====================
__global__ void mask_kernel(const float* __restrict__ x, float* __restrict__ m) {
    int idx = blockIdx.x * blockDim.x + threadIdx.x;
    if (idx < BB * TT) {
        float4 v = ((const float4*)x)[idx];
        m[idx] = (v.x != 0.f || v.y != 0.f || v.z != 0.f || v.w != 0.f) ? 1.f : 0.f;
    }
}

// Build combined block-diagonal U / stacked W / combined bias for fused gru3+gru4 (H=60, I=150)
__global__ void combine34_kernel(const float* __restrict__ W3, const float* __restrict__ U3,
                                 const float* __restrict__ b3, const float* __restrict__ W4,
                                 const float* __restrict__ U4, const float* __restrict__ b4,
                                 float* __restrict__ Uc, float* __restrict__ Wc,
                                 float* __restrict__ bc) {
    const int NU = 60 * 180, NW = 150 * 180, NBc = 2 * 180;
    for (int e = blockIdx.x * blockDim.x + threadIdx.x; e < NU + NW + NBc;
         e += gridDim.x * blockDim.x) {
        if (e < NU) {
            int k = e / 180, col = e % 180;
            int g = col / 60, jj = col % 60;
            float v = 0.f;
            if (jj < 30) { if (k < 30)  v = U3[k * 90 + g * 30 + jj]; }
            else         { if (k >= 30) v = U4[(k - 30) * 90 + g * 30 + (jj - 30)]; }
            Uc[e] = v;
        } else if (e < NU + NW) {
            int e2 = e - NU;
            int i = e2 / 180, col = e2 % 180;
            int g = col / 60, jj = col % 60;
            Wc[e2] = (jj < 30) ? W3[i * 90 + g * 30 + jj] : W4[i * 90 + g * 30 + (jj - 30)];
        } else {
            int e2 = e - NU - NW;
            int rr = e2 / 180, col = e2 % 180;
            int g = col / 60, jj = col % 60;
            bc[e2] = (jj < 30) ? b3[rr * 90 + g * 30 + jj] : b4[rr * 90 + g * 30 + (jj - 30)];
        }
    }
}

__global__ void z_kernel(const float* __restrict__ h34, const float* __restrict__ eps,
                         float* __restrict__ z) {
    int idx = blockIdx.x * blockDim.x + threadIdx.x;
    if (idx < BB * 30) {
        int b = idx / 30, c = idx % 30;
        z[idx] = h34[b * 60 + c] + expf(0.5f * h34[b * 60 + 30 + c]) * eps[idx];
    }
}

__global__ void decin_kernel(const float* __restrict__ z, const float* __restrict__ tin2,
                             const float* __restrict__ masks, float* __restrict__ dec_in) {
    const size_t N = (size_t)BB * TT * 32;
    for (size_t idx = (size_t)blockIdx.x * blockDim.x + threadIdx.x; idx < N;
         idx += (size_t)gridDim.x * blockDim.x) {
        size_t b = idx / ((size_t)TT * 32);
        size_t rem = idx % ((size_t)TT * 32);
        size_t t = rem / 32;
        int c = (int)(rem % 32);
        float v = (c < 30) ? z[b * 30 + c] : tin2[(b * TT + t) * 2 + (c - 30)];
        dec_in[idx] = v * masks[idx];
    }
}

__global__ void dense_kernel(const float* __restrict__ h6, const float* __restrict__ Wd,
                             const float* __restrict__ bd, const float* __restrict__ dec_masks,
                             float* __restrict__ out) {
    int gtid = blockIdx.x * blockDim.x + threadIdx.x;
    int row = gtid >> 5;
    int lane = gtid & 31;
    if (row >= BB * TT) return;
    float s = 0.f;
    const float* hrow = h6 + (size_t)row * 175;
    for (int k = lane; k < 175; k += 32) s = fmaf(hrow[k], Wd[k], s);
#pragma unroll
    for (int off = 16; off; off >>= 1) s += __shfl_down_sync(0xffffffffu, s, off);
    if (lane == 0) out[row] = tanhf(s + bd[0]) * dec_masks[row];
}

// ===================== host-side launch helper =====================
template <int H, int I, bool HARDSIG, bool TANHACT, bool USEMASK, bool WRITESEQ>
static void launch_gru(const float* in_seq, const float* U, const float* W, const float* bias,
                       const float* mask, float* out_seq) {
    constexpr int JT = (H + 7) / 8;
    constexpr int HP = padDim(H), IP = padDim(I);
    constexpr int SM_TOT = 3 * JT * HP + 3 * JT * IP + 2 * 8 * HP + 8 * IP + 4 * JT + 8;
    constexpr int smem_bytes = SM_TOT * 4;
    cudaFuncSetAttribute(gru_kernel<H, I, HARDSIG, TANHACT, USEMASK, WRITESEQ>,
                         cudaFuncAttributeMaxDynamicSharedMemorySize, smem_bytes);
    gru_kernel<H, I, HARDSIG, TANHACT, USEMASK, WRITESEQ>
        <<<128, 256, smem_bytes>>>(in_seq, U, W, bias, mask, out_seq);
}

extern "C" void kernel_launch(void* const* d_in, const int* in_sizes, int n_in,
                              void* d_out, int out_size) {
    const float* x         = (const float*)d_in[0];
    const float* tin2      = (const float*)d_in[1];
    const float* masks     = (const float*)d_in[2];
    const float* dec_masks = (const float*)d_in[3];
    const float* eps       = (const float*)d_in[4];
    const float* W1 = (const float*)d_in[5];
    const float* U1 = (const float*)d_in[6];
    const float* b1 = (const float*)d_in[7];
    const float* W2 = (const float*)d_in[8];
    const float* U2 = (const float*)d_in[9];
    const float* b2 = (const float*)d_in[10];
    const float* W3 = (const float*)d_in[11];
    const float* U3 = (const float*)d_in[12];
    const float* b3 = (const float*)d_in[13];
    const float* W4 = (const float*)d_in[14];
    const float* U4 = (const float*)d_in[15];
    const float* b4 = (const float*)d_in[16];
    const float* W5 = (const float*)d_in[17];
    const float* U5 = (const float*)d_in[18];
    const float* b5 = (const float*)d_in[19];
    const float* W6 = (const float*)d_in[20];
    const float* U6 = (const float*)d_in[21];
    const float* b6 = (const float*)d_in[22];
    const float* Wd = (const float*)d_in[23];
    const float* bd = (const float*)d_in[24];
    float* out = (float*)d_out;

    void *pA, *pB, *pM, *pH34, *pZ, *pUc, *pWc, *pBc;
    cudaGetSymbolAddress(&pA, g_bufA);
    cudaGetSymbolAddress(&pB, g_bufB);
    cudaGetSymbolAddress(&pM, g_mask);
    cudaGetSymbolAddress(&pH34, g_h34);
    cudaGetSymbolAddress(&pZ, g_z);
    cudaGetSymbolAddress(&pUc, g_Uc);
    cudaGetSymbolAddress(&pWc, g_Wc);
    cudaGetSymbolAddress(&pBc, g_bc);
    float* bufA = (float*)pA;
    float* bufB = (float*)pB;
    float* mptr = (float*)pM;
    float* h34  = (float*)pH34;
    float* zbuf = (float*)pZ;
    float* Uc   = (float*)pUc;
    float* Wc   = (float*)pWc;
    float* Bc   = (float*)pBc;

    // 1) input mask from x
    mask_kernel<<<(BB * TT + 255) / 256, 256>>>(x, mptr);

    // 2) encoder GRU1 (H=175, I=4), masked, tanh/hard_sigmoid, full sequence out
    launch_gru<175, 4, true, true, true, true>(x, U1, W1, b1, mptr, bufA);

    // 3) encoder GRU2 (H=150, I=175)
    launch_gru<150, 175, true, true, true, true>(bufA, U2, W2, b2, mptr, bufB);

    // 4) fused GRU3+GRU4 (H=60, I=150), sigmoid recurrent act, linear act, final state only
    combine34_kernel<<<64, 256>>>(W3, U3, b3, W4, U4, b4, Uc, Wc, Bc);
    launch_gru<60, 150, false, false, true, false>(bufB, Uc, Wc, Bc, mptr, h34);

    // 5) reparameterize + decoder input
    z_kernel<<<(BB * 30 + 255) / 256, 256>>>(h34, eps, zbuf);
    decin_kernel<<<1024, 256>>>(zbuf, tin2, masks, bufA);

    // 6) decoder GRU5 (H=150, I=32), no mask
    launch_gru<150, 32, true, true, false, true>(bufA, U5, W5, b5, nullptr, bufB);

    // 7) decoder GRU6 (H=175, I=150), no mask
    launch_gru<175, 150, true, true, false, true>(bufB, U6, W6, b6, nullptr, bufA);

    // 8) dense head + output mask
    dense_kernel<<<(BB * TT + 7) / 8, 256>>>(bufA, Wd, bd, dec_masks, out);
}